// round 10
// baseline (speedup 1.0000x reference)
#include <cuda_runtime.h>
#include <cuda_bf16.h>

// Segment-sum of weighted RGB over sorted ray indices.
// pred_rgb[r, c] = sum_{i : ray_indices[i]==r} weights[i] * rgb[i, c]
//
// R1 structure (best: 19.2us) with IPT 8 -> 4: fewer regs per thread
// (5 vec4 loads instead of 10), ~1.5x resident warps. Probes the
// occupancy x MLP tradeoff from the high-occupancy side.

#define IPT 4  // samples per thread; rgb bytes per thread = 48 (16B-aligned)

__global__ void zero_out_kernel4(float4* __restrict__ out, int n4) {
    int i = blockIdx.x * blockDim.x + threadIdx.x;
    if (i < n4) out[i] = make_float4(0.f, 0.f, 0.f, 0.f);
}
__global__ void zero_out_tail(float* __restrict__ out, int start, int n) {
    int i = start + blockIdx.x * blockDim.x + threadIdx.x;
    if (i < n) out[i] = 0.0f;
}

__global__ __launch_bounds__(256) void integrate_kernel(
    const float4* __restrict__ rgb4,   // 3*N/4 float4
    const float4* __restrict__ w4,     // N/4 float4
    const int4*  __restrict__ idx4,    // N/4 int4
    float* __restrict__ out,
    int n_samples)
{
    int t = blockIdx.x * blockDim.x + threadIdx.x;
    long base = (long)t * IPT;
    if (base >= n_samples) return;

    // ---- 5 independent vector loads per thread ----
    int4   iv = idx4[t];
    float4 wv = w4[t];
    float4 r0 = rgb4[t * 3 + 0];
    float4 r1 = rgb4[t * 3 + 1];
    float4 r2 = rgb4[t * 3 + 2];

    float rf[12] = {r0.x, r0.y, r0.z, r0.w,
                    r1.x, r1.y, r1.z, r1.w,
                    r2.x, r2.y, r2.z, r2.w};
    int   idx[IPT] = {iv.x, iv.y, iv.z, iv.w};
    float w[IPT]   = {wv.x, wv.y, wv.z, wv.w};

    // ---- run-length accumulate over sorted indices, flush on change ----
    int cur = idx[0];
    float a0 = 0.f, a1 = 0.f, a2 = 0.f;
#pragma unroll
    for (int k = 0; k < IPT; k++) {
        int ik = idx[k];
        if (ik != cur) {
            atomicAdd(&out[3 * cur + 0], a0);
            atomicAdd(&out[3 * cur + 1], a1);
            atomicAdd(&out[3 * cur + 2], a2);
            cur = ik;
            a0 = a1 = a2 = 0.f;
        }
        a0 = fmaf(w[k], rf[3 * k + 0], a0);
        a1 = fmaf(w[k], rf[3 * k + 1], a1);
        a2 = fmaf(w[k], rf[3 * k + 2], a2);
    }
    atomicAdd(&out[3 * cur + 0], a0);
    atomicAdd(&out[3 * cur + 1], a1);
    atomicAdd(&out[3 * cur + 2], a2);
}

extern "C" void kernel_launch(void* const* d_in, const int* in_sizes, int n_in,
                              void* d_out, int out_size) {
    const float* rgb = (const float*)d_in[0];
    const float* wts = (const float*)d_in[1];
    const int*   idx = (const int*)d_in[2];
    float* out = (float*)d_out;

    int n_samples = in_sizes[2];

    // zero-init output (poisoned by harness; empty rays must be 0)
    {
        int n4 = out_size / 4;
        int threads = 256;
        int blocks = (n4 + threads - 1) / threads;
        if (blocks > 0)
            zero_out_kernel4<<<blocks, threads>>>((float4*)out, n4);
        if (out_size - n4 * 4 > 0)
            zero_out_tail<<<1, 32>>>(out, n4 * 4, out_size);
    }

    // main segment-sum
    {
        int total_threads = (n_samples + IPT - 1) / IPT;
        int threads = 256;
        int blocks = (total_threads + threads - 1) / threads;
        integrate_kernel<<<blocks, threads>>>(
            (const float4*)rgb, (const float4*)wts, (const int4*)idx,
            out, n_samples);
    }
}

// round 11
// speedup vs baseline: 1.1774x; 1.1774x over previous
#include <cuda_runtime.h>
#include <cuda_bf16.h>

// Segment-sum of weighted RGB over sorted ray indices.
// pred_rgb[r, c] = sum_{i : ray_indices[i]==r} weights[i] * rgb[i, c]
//
// R1 structure (IPT=8 blocked vec4 loads) + per-block SHARED-MEMORY ray
// aggregation: per-thread run-length sums flush to a smem table (ATOMS),
// then one cooperative global-atomic flush of the ~32 rays the tile spans.
// Cuts global REDs ~9x; tests the hypothesis that L2 RED backpressure is
// what has been capping DRAM at ~4.5 TB/s.

#define IPT 8
#define BLOCK 256
#define TILE (BLOCK * IPT)     // 2048 samples per block
#define TABLE 1024             // smem ray slots (tile spans ~32 rays typ.)

__global__ void zero_out_kernel4(float4* __restrict__ out, int n4) {
    int i = blockIdx.x * blockDim.x + threadIdx.x;
    if (i < n4) out[i] = make_float4(0.f, 0.f, 0.f, 0.f);
}
__global__ void zero_out_tail(float* __restrict__ out, int start, int n) {
    int i = start + blockIdx.x * blockDim.x + threadIdx.x;
    if (i < n) out[i] = 0.0f;
}

__global__ __launch_bounds__(BLOCK) void integrate_kernel(
    const float4* __restrict__ rgb4,   // 3*N/4 float4
    const float4* __restrict__ w4,     // N/4 float4
    const int4*  __restrict__ idx4,    // N/4 int4
    const int*   __restrict__ idxs,    // scalar view of ray_indices
    float* __restrict__ out,
    int n_samples)
{
    __shared__ float sacc[TABLE * 3];
    __shared__ int s_base_ray, s_last_ray;

    const int tid = threadIdx.x;
    const long tile_base = (long)blockIdx.x * TILE;
    const int  t = blockIdx.x * BLOCK + tid;
    const long base = (long)t * IPT;
    const bool active = (base < n_samples);

    // ---- zero smem table ----
#pragma unroll
    for (int e = tid; e < TABLE * 3; e += BLOCK) sacc[e] = 0.0f;

    // ---- blocked vector loads (10 independent LDG.128) ----
    int4 i0 = {0,0,0,0}, i1 = {0,0,0,0};
    float4 w0 = {0,0,0,0}, w1 = {0,0,0,0};
    float4 r[6] = {};
    if (active) {
        i0 = idx4[t * 2 + 0];
        i1 = idx4[t * 2 + 1];
        w0 = w4[t * 2 + 0];
        w1 = w4[t * 2 + 1];
#pragma unroll
        for (int k = 0; k < 6; k++) r[k] = rgb4[t * 6 + k];
    }

    // tile ray range (uniform): first sample's and last sample's ray
    if (tid == 0) {
        s_base_ray = (tile_base < n_samples) ? idxs[tile_base] : 0;
        long last = tile_base + TILE - 1;
        if (last >= n_samples) last = n_samples - 1;
        s_last_ray = (last >= 0) ? idxs[last] : 0;
    }
    __syncthreads();
    const int base_ray = s_base_ray;

    if (active) {
        const float* rf = reinterpret_cast<const float*>(r);
        int   idx[IPT] = {i0.x, i0.y, i0.z, i0.w, i1.x, i1.y, i1.z, i1.w};
        float w[IPT]   = {w0.x, w0.y, w0.z, w0.w, w1.x, w1.y, w1.z, w1.w};
        const int nval = (int)min((long)IPT, n_samples - base);

        int cur = idx[0];
        float a0 = 0.f, a1 = 0.f, a2 = 0.f;
#pragma unroll
        for (int k = 0; k < IPT; k++) {
            if (k >= nval) break;
            int ik = idx[k];
            if (ik != cur) {
                int off = cur - base_ray;
                if (off < TABLE) {
                    atomicAdd(&sacc[3 * off + 0], a0);
                    atomicAdd(&sacc[3 * off + 1], a1);
                    atomicAdd(&sacc[3 * off + 2], a2);
                } else {
                    atomicAdd(&out[3 * cur + 0], a0);
                    atomicAdd(&out[3 * cur + 1], a1);
                    atomicAdd(&out[3 * cur + 2], a2);
                }
                cur = ik;
                a0 = a1 = a2 = 0.f;
            }
            a0 = fmaf(w[k], rf[3 * k + 0], a0);
            a1 = fmaf(w[k], rf[3 * k + 1], a1);
            a2 = fmaf(w[k], rf[3 * k + 2], a2);
        }
        {
            int off = cur - base_ray;
            if (off < TABLE) {
                atomicAdd(&sacc[3 * off + 0], a0);
                atomicAdd(&sacc[3 * off + 1], a1);
                atomicAdd(&sacc[3 * off + 2], a2);
            } else {
                atomicAdd(&out[3 * cur + 0], a0);
                atomicAdd(&out[3 * cur + 1], a1);
                atomicAdd(&out[3 * cur + 2], a2);
            }
        }
    }
    __syncthreads();

    // ---- cooperative global flush of the tile's ray range ----
    int n_range = s_last_ray - base_ray + 1;
    if (n_range > TABLE) n_range = TABLE;
    if (n_range < 0) n_range = 0;
    for (int e = tid; e < n_range * 3; e += BLOCK) {
        float v = sacc[e];
        if (v != 0.0f)
            atomicAdd(&out[3 * base_ray + e], v);
    }
}

extern "C" void kernel_launch(void* const* d_in, const int* in_sizes, int n_in,
                              void* d_out, int out_size) {
    const float* rgb = (const float*)d_in[0];
    const float* wts = (const float*)d_in[1];
    const int*   idx = (const int*)d_in[2];
    float* out = (float*)d_out;

    int n_samples = in_sizes[2];

    // zero-init output (poisoned by harness; empty rays must be 0)
    {
        int n4 = out_size / 4;
        int threads = 256;
        int blocks = (n4 + threads - 1) / threads;
        if (blocks > 0)
            zero_out_kernel4<<<blocks, threads>>>((float4*)out, n4);
        if (out_size - n4 * 4 > 0)
            zero_out_tail<<<1, 32>>>(out, n4 * 4, out_size);
    }

    // main segment-sum
    {
        int blocks = (n_samples + TILE - 1) / TILE;
        integrate_kernel<<<blocks, BLOCK>>>(
            (const float4*)rgb, (const float4*)wts, (const int4*)idx,
            idx, out, n_samples);
    }
}